// round 1
// baseline (speedup 1.0000x reference)
#include <cuda_runtime.h>
#include <stdint.h>

#define OUTPUT_DIM 64
#define NB_CTRL_SIG 16
#define FULL_DIM (OUTPUT_DIM * NB_CTRL_SIG)   // 1024
#define VEC 4                                 // float4 per thread
#define THREADS_PER_ROW (OUTPUT_DIM / VEC)    // 16

// out[b, j] = full_input[b, idx[b]*64 + j]
__global__ void multiplexer_kernel(const float4* __restrict__ full_input,
                                   const int* __restrict__ indices,
                                   float4* __restrict__ out,
                                   int batch) {
    int tid = blockIdx.x * blockDim.x + threadIdx.x;   // global float4 slot
    int b   = tid / THREADS_PER_ROW;
    int j   = tid % THREADS_PER_ROW;                   // float4 index within row
    if (b >= batch) return;

    int idx = __ldg(&indices[b]);                      // broadcast within the 16-thread group (L1 hit)
    // full_input row stride in float4s = 1024/4 = 256; block offset = idx*64/4 = idx*16
    const float4 v = __ldg(&full_input[(size_t)b * (FULL_DIM / VEC) + idx * THREADS_PER_ROW + j]);
    out[(size_t)b * THREADS_PER_ROW + j] = v;
}

extern "C" void kernel_launch(void* const* d_in, const int* in_sizes, int n_in,
                              void* d_out, int out_size) {
    const float4* full_input = (const float4*)d_in[0];
    const int*    indices    = (const int*)d_in[1];
    float4*       out        = (float4*)d_out;

    int batch = in_sizes[1];                       // 262144 indices
    int total_threads = batch * THREADS_PER_ROW;   // 4,194,304
    int block = 256;
    int grid  = (total_threads + block - 1) / block;

    multiplexer_kernel<<<grid, block>>>(full_input, indices, out, batch);
}

// round 2
// speedup vs baseline: 1.3411x; 1.3411x over previous
#include <cuda_runtime.h>
#include <stdint.h>

#define OUTPUT_DIM 64
#define NB_CTRL_SIG 16
#define FULL_DIM (OUTPUT_DIM * NB_CTRL_SIG)   // 1024
#define VEC 4                                 // float4 per slot
#define SLOTS_PER_ROW (OUTPUT_DIM / VEC)      // 16
#define UNROLL 4

// out[b, j] = full_input[b, idx[b]*64 + j]
// Each thread handles UNROLL float4 slots, strided by the total thread count,
// so per-slot coalescing is identical to the 1-slot version but MLP = UNROLL.
__global__ void multiplexer_kernel(const float4* __restrict__ full_input,
                                   const int* __restrict__ indices,
                                   float4* __restrict__ out,
                                   int total_slots, int stride_slots) {
    int s0 = blockIdx.x * blockDim.x + threadIdx.x;

    int s1 = s0 + stride_slots;
    int s2 = s1 + stride_slots;
    int s3 = s2 + stride_slots;

    if (s3 < total_slots) {
        // fast path: all four slots valid (always taken for this problem size)
        int b0 = s0 >> 4, j0 = s0 & 15;
        int b1 = s1 >> 4, j1 = s1 & 15;
        int b2 = s2 >> 4, j2 = s2 & 15;
        int b3 = s3 >> 4, j3 = s3 & 15;

        int i0 = __ldg(&indices[b0]);
        int i1 = __ldg(&indices[b1]);
        int i2 = __ldg(&indices[b2]);
        int i3 = __ldg(&indices[b3]);

        float4 v0 = __ldg(&full_input[(size_t)b0 * (FULL_DIM / VEC) + i0 * SLOTS_PER_ROW + j0]);
        float4 v1 = __ldg(&full_input[(size_t)b1 * (FULL_DIM / VEC) + i1 * SLOTS_PER_ROW + j1]);
        float4 v2 = __ldg(&full_input[(size_t)b2 * (FULL_DIM / VEC) + i2 * SLOTS_PER_ROW + j2]);
        float4 v3 = __ldg(&full_input[(size_t)b3 * (FULL_DIM / VEC) + i3 * SLOTS_PER_ROW + j3]);

        out[s0] = v0;
        out[s1] = v1;
        out[s2] = v2;
        out[s3] = v3;
    } else {
        #pragma unroll
        for (int u = 0; u < UNROLL; u++) {
            int s = s0 + u * stride_slots;
            if (s < total_slots) {
                int b = s >> 4, j = s & 15;
                int i = __ldg(&indices[b]);
                out[s] = __ldg(&full_input[(size_t)b * (FULL_DIM / VEC) + i * SLOTS_PER_ROW + j]);
            }
        }
    }
}

extern "C" void kernel_launch(void* const* d_in, const int* in_sizes, int n_in,
                              void* d_out, int out_size) {
    const float4* full_input = (const float4*)d_in[0];
    const int*    indices    = (const int*)d_in[1];
    float4*       out        = (float4*)d_out;

    int batch       = in_sizes[1];                 // 262144
    int total_slots = batch * SLOTS_PER_ROW;       // 4,194,304 float4 slots
    int block       = 256;
    int threads     = (total_slots + UNROLL - 1) / UNROLL;  // 1,048,576
    int grid        = (threads + block - 1) / block;        // 4096
    int stride      = grid * block;                // slot stride between unroll legs

    multiplexer_kernel<<<grid, block>>>(full_input, indices, out, total_slots, stride);
}